// round 6
// baseline (speedup 1.0000x reference)
#include <cuda_runtime.h>

#define NN 100000
#define EE 3200000
#define NG 100
#define NPER 1000
#define EPG 32000
#define KTOP 800

// ---------------- global scratch (static; no cudaMalloc) ----------------
__device__ int    g_off[NN + 1];
__device__ int    g_csr[EE];
__device__ float  g_dis[NN];
__device__ float  g_p[NN];             // h . w_rel
__device__ float  g_hr[NN];            // h . w_root
__device__ float4 g_contrib[NN * 4];   // (x@W1) * dis  [N,16]
__device__ float4 g_h4[NN * 4];        // conv1 output  [N,16]

// ============ fused CSR build: block-per-graph histogram + scan + scatter ============
__global__ void __launch_bounds__(1024) k_build(const int* __restrict__ src,
                                                const int* __restrict__ dst) {
    __shared__ int sdeg[1024];
    __shared__ int soff[1024];
    __shared__ int scur[NPER];
    int g = blockIdx.x, t = threadIdx.x;
    int ebase = g * EPG, nbase = g * NPER;
    sdeg[t] = 0;
    __syncthreads();
    for (int e = t; e < EPG; e += 1024)
        atomicAdd(&sdeg[dst[ebase + e] - nbase], 1);
    __syncthreads();
    int v = sdeg[t];
    soff[t] = v;
    __syncthreads();
    for (int d = 1; d < 1024; d <<= 1) {
        int cur = soff[t];
        int add = (t >= d) ? soff[t - d] : 0;
        __syncthreads();
        soff[t] = cur + add;
        __syncthreads();
    }
    int excl = soff[t] - v;
    if (t < NPER) {
        g_off[nbase + t] = ebase + excl;
        scur[t] = excl;
        g_dis[nbase + t] = rsqrtf((float)(sdeg[t] + 1));
    }
    if (g == NG - 1 && t == 0) g_off[NN] = EE;
    __syncthreads();
    for (int e = t; e < EPG; e += 1024) {
        int d = dst[ebase + e] - nbase;
        int p = atomicAdd(&scur[d], 1);
        g_csr[ebase + p] = src[ebase + e];
    }
}

// ============ GEMM1: contrib = (x @ W1) * dis ============
__global__ void k_gemm1(const float* __restrict__ x, const float* __restrict__ W1) {
    __shared__ float xs[64 * 129];
    __shared__ float ws[128 * 16];
    int tid = threadIdx.x;
    int v0 = blockIdx.x * 64;
    for (int i = tid; i < 2048; i += 256) ws[i] = W1[i];
    const float4* x4 = (const float4*)x;
    for (int i = tid; i < 64 * 32; i += 256) {
        int r = i >> 5, c = i & 31;
        int v = v0 + r;
        float4 val = (v < NN) ? x4[(size_t)v * 32 + c] : make_float4(0.f, 0.f, 0.f, 0.f);
        float* p = &xs[r * 129 + c * 4];
        p[0] = val.x; p[1] = val.y; p[2] = val.z; p[3] = val.w;
    }
    __syncthreads();
    int n = tid & 63;
    int jg = tid >> 6;
    float4 acc = make_float4(0.f, 0.f, 0.f, 0.f);
    const float4* ws4 = (const float4*)ws;
    const float* xr = &xs[n * 129];
#pragma unroll 8
    for (int k = 0; k < 128; k++) {
        float xv = xr[k];
        float4 w = ws4[k * 4 + jg];
        acc.x += xv * w.x; acc.y += xv * w.y; acc.z += xv * w.z; acc.w += xv * w.w;
    }
    int v = v0 + n;
    if (v < NN) {
        float d = g_dis[v];
        acc.x *= d; acc.y *= d; acc.z *= d; acc.w *= d;
        g_contrib[v * 4 + jg] = acc;
    }
}

// ============ conv1: SMEM-tile gather. 2 blocks/graph x 512 thr, dyn smem = 64000B ====
// lane layout: hh = lane>>4 (edge slot parity), f = lane&15 (feature)
__global__ void __launch_bounds__(512) k_conv1(const float* __restrict__ b1,
                                               const float* __restrict__ wrel,
                                               const float* __restrict__ wroot) {
    extern __shared__ float tile[];   // contrib for whole graph [1000][16]
    int g = blockIdx.x >> 1;
    int half = blockIdx.x & 1;
    int nbase = g * NPER;
    int tid = threadIdx.x;
    const float4* src4 = (const float4*)&g_contrib[nbase * 4];
    for (int i = tid; i < NPER * 4; i += 512) ((float4*)tile)[i] = src4[i];
    __syncthreads();
    int wid = tid >> 5, lane = tid & 31;
    int hh = lane >> 4, f = lane & 15;
    float bf = __ldg(&b1[f]);
    float wrf = __ldg(&wrel[f]);
    float wof = __ldg(&wroot[f]);
    int vend = half * 500 + 500;
    for (int vl = half * 500 + wid; vl < vend; vl += 16) {
        int v = nbase + vl;
        int beg = g_off[v], end = g_off[v + 1];
        float acc = 0.f;
        for (int i = beg + hh; i < end; i += 2) {
            int u = __ldg(&g_csr[i]) - nbase;
            acc += tile[u * 16 + f];
        }
        acc += __shfl_xor_sync(0xffffffffu, acc, 16);
        float d = g_dis[v];
        float hv = fmaxf(fmaf(d, acc + tile[vl * 16 + f], bf), 0.f);
        if (hh == 0) ((float*)g_h4)[v * 16 + f] = hv;
        float pp = hv * wrf;
        float rr = hv * wof;
#pragma unroll
        for (int m = 1; m < 16; m <<= 1) {
            pp += __shfl_xor_sync(0xffffffffu, pp, m);
            rr += __shfl_xor_sync(0xffffffffu, rr, m);
        }
        if (lane == 0) { g_p[v] = pp; g_hr[v] = rr; }
    }
}

// ============ megakernel: score + top-K + deg2 + c2 + conv2 + GEMM2/relu/mean-pool ====
// block-per-graph, 1024 threads, dyn smem 105600B
__global__ void __launch_bounds__(1024) k_mega(const float* __restrict__ brel,
                                               const float* __restrict__ W2,
                                               const float* __restrict__ b2,
                                               float* __restrict__ out) {
    extern __shared__ unsigned long long dynbuf[];
    unsigned long long* keys = dynbuf;                 // [1024]  8192B
    float* fp    = (float*)(dynbuf + 1024);
    float* p_s   = fp;                                 // [1000]
    float* sc_s  = fp + 1000;                          // [1000]
    float* d2_s  = fp + 2000;                          // [1000]
    float* smask = fp + 3000;                          // [1000]
    float* c2    = fp + 4000;                          // [1000*16]
    float* w2s   = fp + 20000;                         // [16*256]
    float* oacc  = fp + 24096;                         // [256]

    int g = blockIdx.x, t = threadIdx.x;
    int nbase = g * NPER;
    int wid = t >> 5, lane = t & 31;

    // load p tile + W2 + init oacc
    if (t < NPER) p_s[t] = g_p[nbase + t];
    for (int i = t; i < 4096; i += 1024) w2s[i] = W2[i];
    if (t < 256) oacc[t] = 0.f;
    __syncthreads();

    // ---- score: gather p from SMEM ----
    float bre = __ldg(brel);
    for (int vl = wid; vl < NPER; vl += 32) {
        int v = nbase + vl;
        int beg = g_off[v], end = g_off[v + 1];
        float s = 0.f;
        for (int i = beg + lane; i < end; i += 32)
            s += p_s[__ldg(&g_csr[i]) - nbase];
#pragma unroll
        for (int m = 16; m; m >>= 1) s += __shfl_xor_sync(0xffffffffu, s, m);
        if (lane == 0) sc_s[vl] = tanhf(s + g_hr[v] + bre);
    }
    __syncthreads();

    // ---- bitonic top-K over 1024 keys ----
    if (t < NPER) {
        unsigned u = __float_as_uint(sc_s[t]);
        u = (u & 0x80000000u) ? ~u : (u | 0x80000000u);
        keys[t] = ((unsigned long long)u << 32) | (unsigned)(~t);   // ties: lower idx wins
    } else {
        keys[t] = 0ull;
    }
    __syncthreads();
    for (int k = 2; k <= 1024; k <<= 1) {
        for (int j = k >> 1; j > 0; j >>= 1) {
            int ixj = t ^ j;
            if (ixj > t) {
                unsigned long long a = keys[t], b = keys[ixj];
                bool up = ((t & k) == 0);
                if ((a > b) == up) { keys[t] = b; keys[ixj] = a; }
            }
            __syncthreads();
        }
    }
    if (t >= (1024 - NPER)) {
        unsigned idx = ~(unsigned)(keys[t] & 0xFFFFFFFFull);
        smask[idx] = (t >= 1024 - KTOP) ? 1.0f : 0.0f;
    }
    __syncthreads();

    // ---- deg2 / dis2 under mask (smask from SMEM) ----
    for (int vl = wid; vl < NPER; vl += 32) {
        int v = nbase + vl;
        int beg = g_off[v], end = g_off[v + 1];
        float s = 0.f;
        for (int i = beg + lane; i < end; i += 32)
            s += smask[__ldg(&g_csr[i]) - nbase];
#pragma unroll
        for (int m = 16; m; m >>= 1) s += __shfl_xor_sync(0xffffffffu, s, m);
        float mv = smask[vl];
        if (lane == 0) d2_s[vl] = (mv > 0.f) ? rsqrtf(mv + s) : 0.f;
    }
    __syncthreads();

    // ---- c2 tile = h * score * dis2 (coalesced h read) ----
    {
        const float4* h4 = (const float4*)&g_h4[nbase * 4];
        float4* c24 = (float4*)c2;
        for (int i = t; i < NPER * 4; i += 1024) {
            int vl = i >> 2;
            float f = sc_s[vl] * d2_s[vl];
            float4 h = h4[i];
            c24[i] = make_float4(h.x * f, h.y * f, h.z * f, h.w * f);
        }
    }
    __syncthreads();

    // ---- conv2 gather (SMEM tile) + fused GEMM2(16->256) + relu + pool ----
    int hh = lane >> 4, f = lane & 15;
    float bb[8], pacc[8];
#pragma unroll
    for (int k = 0; k < 8; k++) {
        bb[k] = __ldg(&b2[k * 32 + lane]);
        pacc[k] = 0.f;
    }
    for (int vl = wid; vl < NPER; vl += 32) {
        float d2 = d2_s[vl];
        if (d2 == 0.f) continue;       // masked-out node contributes nothing
        int v = nbase + vl;
        int beg = g_off[v], end = g_off[v + 1];
        float acc = 0.f;
        for (int i = beg + hh; i < end; i += 2) {
            int u = __ldg(&g_csr[i]) - nbase;
            acc += c2[u * 16 + f];
        }
        acc += __shfl_xor_sync(0xffffffffu, acc, 16);
        float gg = d2 * (acc + c2[vl * 16 + f]);   // lane f holds feature f (dup in halves)
        // GEMM row: out_j += relu(sum_f gg_f * W2[f][j] + b2[j]), j = k*32+lane
        float s0 = bb[0], s1 = bb[1], s2 = bb[2], s3 = bb[3];
        float s4 = bb[4], s5 = bb[5], s6 = bb[6], s7 = bb[7];
#pragma unroll
        for (int ff = 0; ff < 16; ff++) {
            float gf = __shfl_sync(0xffffffffu, gg, ff);
            const float* wrow = &w2s[ff * 256 + lane];
            s0 = fmaf(gf, wrow[0],   s0);
            s1 = fmaf(gf, wrow[32],  s1);
            s2 = fmaf(gf, wrow[64],  s2);
            s3 = fmaf(gf, wrow[96],  s3);
            s4 = fmaf(gf, wrow[128], s4);
            s5 = fmaf(gf, wrow[160], s5);
            s6 = fmaf(gf, wrow[192], s6);
            s7 = fmaf(gf, wrow[224], s7);
        }
        pacc[0] += fmaxf(s0, 0.f); pacc[1] += fmaxf(s1, 0.f);
        pacc[2] += fmaxf(s2, 0.f); pacc[3] += fmaxf(s3, 0.f);
        pacc[4] += fmaxf(s4, 0.f); pacc[5] += fmaxf(s5, 0.f);
        pacc[6] += fmaxf(s6, 0.f); pacc[7] += fmaxf(s7, 0.f);
    }
#pragma unroll
    for (int k = 0; k < 8; k++) atomicAdd(&oacc[k * 32 + lane], pacc[k]);
    __syncthreads();
    if (t < 256) out[g * 256 + t] = oacc[t] * (1.0f / (float)KTOP);
}

// ============ launch ============
extern "C" void kernel_launch(void* const* d_in, const int* in_sizes, int n_in,
                              void* d_out, int out_size) {
    const float* x     = (const float*)d_in[0];
    const int*   ei    = (const int*)d_in[1];
    const float* W1    = (const float*)d_in[3];
    const float* b1    = (const float*)d_in[4];
    const float* wrel  = (const float*)d_in[5];
    const float* brel  = (const float*)d_in[6];
    const float* wroot = (const float*)d_in[7];
    const float* W2    = (const float*)d_in[8];
    const float* b2    = (const float*)d_in[9];
    float* out = (float*)d_out;

    const int* src = ei;
    const int* dst = ei + EE;

    const int CONV1_SMEM = NPER * 16 * 4;               // 64000
    const int MEGA_SMEM  = 8192 + (24096 + 256) * 4;    // 105600
    cudaFuncSetAttribute(k_conv1, cudaFuncAttributeMaxDynamicSharedMemorySize, CONV1_SMEM);
    cudaFuncSetAttribute(k_mega,  cudaFuncAttributeMaxDynamicSharedMemorySize, MEGA_SMEM);

    k_build<<<NG, 1024>>>(src, dst);
    k_gemm1<<<(NN + 63) / 64, 256>>>(x, W1);
    k_conv1<<<NG * 2, 512, CONV1_SMEM>>>(b1, wrel, wroot);
    k_mega<<<NG, 1024, MEGA_SMEM>>>(brel, W2, b2, out);
}

// round 7
// speedup vs baseline: 1.2490x; 1.2490x over previous
#include <cuda_runtime.h>

#define NN 100000
#define EE 3200000
#define NG 100
#define NPER 1000
#define EPG 32000
#define KTOP 800

// ---------------- global scratch (static; no cudaMalloc) ----------------
__device__ int    g_off[NN + 1];
__device__ int    g_csr[EE];
__device__ int    g_rank[EE];          // per-edge rank within its dst bucket
__device__ float  g_dis[NN];
__device__ float  g_dis2[NN];
__device__ float  g_p[NN];             // h . w_rel
__device__ float  g_hr[NN];            // h . w_root
__device__ float4 g_contrib[NN * 4];   // (x@W1) * dis  [N,16]
__device__ float4 g_h4[NN * 4];        // conv1 output  [N,16]
__device__ float4 g_gg[NN * 4];        // conv2 agg (pre-W2) [N,16]

// ============ CSR build: histogram (rank-capturing) + scan + atomic-free scatter ====
__global__ void __launch_bounds__(1024) k_build(const int* __restrict__ src,
                                                const int* __restrict__ dst) {
    __shared__ int sdeg[1024];
    __shared__ int soff[1024];
    int g = blockIdx.x, t = threadIdx.x;
    int ebase = g * EPG, nbase = g * NPER;
    sdeg[t] = 0;
    __syncthreads();
    // histogram; the atomic's return value is this edge's scatter rank
    for (int e = t; e < EPG; e += 1024) {
        int d = dst[ebase + e] - nbase;
        g_rank[ebase + e] = atomicAdd(&sdeg[d], 1);
    }
    __syncthreads();
    // inclusive Hillis-Steele scan of degrees
    int v = sdeg[t];
    soff[t] = v;
    __syncthreads();
    for (int d = 1; d < 1024; d <<= 1) {
        int cur = soff[t];
        int add = (t >= d) ? soff[t - d] : 0;
        __syncthreads();
        soff[t] = cur + add;
        __syncthreads();
    }
    int excl = soff[t] - v;
    if (t < NPER) {
        g_off[nbase + t] = ebase + excl;
        g_dis[nbase + t] = rsqrtf((float)(v + 1));   // + self-loop
    }
    if (g == NG - 1 && t == 0) g_off[NN] = EE;
    sdeg[t] = excl;                                  // reuse as exclusive offsets
    __syncthreads();
    // atomic-free scatter
    for (int e = t; e < EPG; e += 1024) {
        int d = dst[ebase + e] - nbase;
        g_csr[ebase + sdeg[d] + g_rank[ebase + e]] = src[ebase + e];
    }
}

// ============ GEMM1: contrib = (x @ W1) * dis ============
__global__ void k_gemm1(const float* __restrict__ x, const float* __restrict__ W1) {
    __shared__ float xs[64 * 129];
    __shared__ float ws[128 * 16];
    int tid = threadIdx.x;
    int v0 = blockIdx.x * 64;
    for (int i = tid; i < 2048; i += 256) ws[i] = W1[i];
    const float4* x4 = (const float4*)x;
    for (int i = tid; i < 64 * 32; i += 256) {
        int r = i >> 5, c = i & 31;
        int v = v0 + r;
        float4 val = (v < NN) ? x4[(size_t)v * 32 + c] : make_float4(0.f, 0.f, 0.f, 0.f);
        float* p = &xs[r * 129 + c * 4];
        p[0] = val.x; p[1] = val.y; p[2] = val.z; p[3] = val.w;
    }
    __syncthreads();
    int n = tid & 63;
    int jg = tid >> 6;
    float4 acc = make_float4(0.f, 0.f, 0.f, 0.f);
    const float4* ws4 = (const float4*)ws;
    const float* xr = &xs[n * 129];
#pragma unroll 8
    for (int k = 0; k < 128; k++) {
        float xv = xr[k];
        float4 w = ws4[k * 4 + jg];
        acc.x += xv * w.x; acc.y += xv * w.y; acc.z += xv * w.z; acc.w += xv * w.w;
    }
    int v = v0 + n;
    if (v < NN) {
        float d = g_dis[v];
        acc.x *= d; acc.y *= d; acc.z *= d; acc.w *= d;
        g_contrib[v * 4 + jg] = acc;
    }
}

// ============ conv1: SMEM-tile gather. 4 blocks/graph x 512 thr ============
// lane layout: hh = lane>>4 (edge parity), f = lane&15 (feature)
__global__ void __launch_bounds__(512) k_conv1(const float* __restrict__ b1,
                                               const float* __restrict__ wrel,
                                               const float* __restrict__ wroot) {
    extern __shared__ float tile[];   // contrib for whole graph [1000][16]
    int g = blockIdx.x >> 2;
    int quarter = blockIdx.x & 3;
    int nbase = g * NPER;
    int tid = threadIdx.x;
    const float4* src4 = (const float4*)&g_contrib[nbase * 4];
    for (int i = tid; i < NPER * 4; i += 512) ((float4*)tile)[i] = src4[i];
    __syncthreads();
    int wid = tid >> 5, lane = tid & 31;
    int hh = lane >> 4, f = lane & 15;
    float bf = __ldg(&b1[f]);
    float wrf = __ldg(&wrel[f]);
    float wof = __ldg(&wroot[f]);
    int vbeg = quarter * 250, vend = vbeg + 250;
    for (int vl = vbeg + wid; vl < vend; vl += 16) {
        int v = nbase + vl;
        int beg = g_off[v], end = g_off[v + 1];
        float acc = 0.f;
        for (int i = beg + hh; i < end; i += 2) {
            int u = __ldg(&g_csr[i]) - nbase;
            acc += tile[u * 16 + f];
        }
        acc += __shfl_xor_sync(0xffffffffu, acc, 16);
        float d = g_dis[v];
        float hv = fmaxf(fmaf(d, acc + tile[vl * 16 + f], bf), 0.f);
        if (hh == 0) ((float*)g_h4)[v * 16 + f] = hv;
        float pp = hv * wrf;
        float rr = hv * wof;
#pragma unroll
        for (int m = 1; m < 16; m <<= 1) {
            pp += __shfl_xor_sync(0xffffffffu, pp, m);
            rr += __shfl_xor_sync(0xffffffffu, rr, m);
        }
        if (lane == 0) { g_p[v] = pp; g_hr[v] = rr; }
    }
}

// ============ k_light: score + top-K + deg2 + c2 + conv2-gather (all SMEM) ============
// block-per-graph, 1024 threads, dyn smem 88192B
__global__ void __launch_bounds__(1024) k_light(const float* __restrict__ brel,
                                                float* __restrict__ outdummy) {
    extern __shared__ unsigned long long dynbuf[];
    unsigned long long* keys = dynbuf;                 // [1024]
    float* fp    = (float*)(dynbuf + 1024);
    float* p_s   = fp;                                 // [1000]
    float* sc_s  = fp + 1000;                          // [1000]
    float* d2_s  = fp + 2000;                          // [1000]
    float* smask = fp + 3000;                          // [1000]
    float* c2    = fp + 4000;                          // [1000*16]

    int g = blockIdx.x, t = threadIdx.x;
    int nbase = g * NPER;
    int wid = t >> 5, lane = t & 31;

    if (t < NPER) p_s[t] = g_p[nbase + t];
    __syncthreads();

    // ---- score ----
    float bre = __ldg(brel);
    for (int vl = wid; vl < NPER; vl += 32) {
        int v = nbase + vl;
        int beg = g_off[v], end = g_off[v + 1];
        float s = 0.f;
        for (int i = beg + lane; i < end; i += 32)
            s += p_s[__ldg(&g_csr[i]) - nbase];
#pragma unroll
        for (int m = 16; m; m >>= 1) s += __shfl_xor_sync(0xffffffffu, s, m);
        if (lane == 0) sc_s[vl] = tanhf(s + g_hr[v] + bre);
    }
    __syncthreads();

    // ---- bitonic top-K ----
    if (t < NPER) {
        unsigned u = __float_as_uint(sc_s[t]);
        u = (u & 0x80000000u) ? ~u : (u | 0x80000000u);
        keys[t] = ((unsigned long long)u << 32) | (unsigned)(~t);   // ties: lower idx wins
    } else {
        keys[t] = 0ull;
    }
    __syncthreads();
    for (int k = 2; k <= 1024; k <<= 1) {
        for (int j = k >> 1; j > 0; j >>= 1) {
            int ixj = t ^ j;
            if (ixj > t) {
                unsigned long long a = keys[t], b = keys[ixj];
                bool up = ((t & k) == 0);
                if ((a > b) == up) { keys[t] = b; keys[ixj] = a; }
            }
            __syncthreads();
        }
    }
    if (t >= (1024 - NPER)) {
        unsigned idx = ~(unsigned)(keys[t] & 0xFFFFFFFFull);
        smask[idx] = (t >= 1024 - KTOP) ? 1.0f : 0.0f;
    }
    __syncthreads();

    // ---- deg2 / dis2 ----
    for (int vl = wid; vl < NPER; vl += 32) {
        int v = nbase + vl;
        int beg = g_off[v], end = g_off[v + 1];
        float s = 0.f;
        for (int i = beg + lane; i < end; i += 32)
            s += smask[__ldg(&g_csr[i]) - nbase];
#pragma unroll
        for (int m = 16; m; m >>= 1) s += __shfl_xor_sync(0xffffffffu, s, m);
        float mv = smask[vl];
        if (lane == 0) {
            float d2 = (mv > 0.f) ? rsqrtf(mv + s) : 0.f;
            d2_s[vl] = d2;
            g_dis2[v] = d2;
        }
    }
    __syncthreads();

    // ---- c2 tile = h * score * dis2 ----
    {
        const float4* h4 = (const float4*)&g_h4[nbase * 4];
        float4* c24 = (float4*)c2;
        for (int i = t; i < NPER * 4; i += 1024) {
            int vl = i >> 2;
            float f = sc_s[vl] * d2_s[vl];
            float4 h = h4[i];
            c24[i] = make_float4(h.x * f, h.y * f, h.z * f, h.w * f);
        }
    }
    __syncthreads();

    // ---- conv2 gather from SMEM tile: gg = dis2*(S + c2[v]) ----
    int hh = lane >> 4, f = lane & 15;
    for (int vl = wid; vl < NPER; vl += 32) {
        float d2 = d2_s[vl];
        if (d2 == 0.f) continue;                     // masked node: gg stays 0 (gated in pool)
        int v = nbase + vl;
        int beg = g_off[v], end = g_off[v + 1];
        float acc = 0.f;
        for (int i = beg + hh; i < end; i += 2) {
            int u = __ldg(&g_csr[i]) - nbase;
            acc += c2[u * 16 + f];
        }
        acc += __shfl_xor_sync(0xffffffffu, acc, 16);
        float gv = d2 * (acc + c2[vl * 16 + f]);
        if (hh == 0) ((float*)g_gg)[v * 16 + f] = gv;
    }
    (void)outdummy;
}

// ============ fused GEMM2(16->256) + relu + masked mean pool (W2 in registers) ========
__global__ void k_pool(const float* __restrict__ W2, const float* __restrict__ b2,
                       float* __restrict__ out) {
    __shared__ float gs[16][16];
    __shared__ float ms[16];
    int t = threadIdx.x;
    int gi = blockIdx.x >> 3;
    int part = blockIdx.x & 7;
    int node0 = gi * NPER + part * 125;
    float w0[16], w1[16];
#pragma unroll
    for (int m = 0; m < 16; m++) {
        w0[m] = __ldg(&W2[m * 256 + t]);
        w1[m] = __ldg(&W2[m * 256 + t + 128]);
    }
    float bb0 = __ldg(&b2[t]), bb1 = __ldg(&b2[t + 128]);
    float acc0 = 0.f, acc1 = 0.f;
    const float* gflat = (const float*)g_gg;
    for (int base = 0; base < 125; base += 16) {
        int ns = min(16, 125 - base);
        for (int i = t; i < ns * 16; i += 128)
            ((float*)gs)[i] = gflat[(node0 + base) * 16 + i];
        if (t < ns) ms[t] = g_dis2[node0 + base + t];   // != 0 iff node survives
        __syncthreads();
        for (int q = 0; q < ns; q++) {
            if (ms[q] != 0.f) {
                float s0 = bb0, s1 = bb1;
#pragma unroll
                for (int m = 0; m < 16; m++) {
                    float gv = gs[q][m];
                    s0 = fmaf(gv, w0[m], s0);
                    s1 = fmaf(gv, w1[m], s1);
                }
                acc0 += fmaxf(s0, 0.f);
                acc1 += fmaxf(s1, 0.f);
            }
        }
        __syncthreads();
    }
    const float inv = 1.0f / (float)KTOP;
    atomicAdd(&out[gi * 256 + t], acc0 * inv);
    atomicAdd(&out[gi * 256 + t + 128], acc1 * inv);
}

// ============ launch ============
extern "C" void kernel_launch(void* const* d_in, const int* in_sizes, int n_in,
                              void* d_out, int out_size) {
    const float* x     = (const float*)d_in[0];
    const int*   ei    = (const int*)d_in[1];
    const float* W1    = (const float*)d_in[3];
    const float* b1    = (const float*)d_in[4];
    const float* wrel  = (const float*)d_in[5];
    const float* brel  = (const float*)d_in[6];
    const float* wroot = (const float*)d_in[7];
    const float* W2    = (const float*)d_in[8];
    const float* b2    = (const float*)d_in[9];
    float* out = (float*)d_out;

    const int* src = ei;
    const int* dst = ei + EE;

    const int CONV1_SMEM = NPER * 16 * 4;        // 64000
    const int LIGHT_SMEM = 8192 + 20000 * 4;     // 88192
    cudaFuncSetAttribute(k_conv1, cudaFuncAttributeMaxDynamicSharedMemorySize, CONV1_SMEM);
    cudaFuncSetAttribute(k_light, cudaFuncAttributeMaxDynamicSharedMemorySize, LIGHT_SMEM);

    cudaMemsetAsync(d_out, 0, (size_t)out_size * sizeof(float), 0);

    k_build<<<NG, 1024>>>(src, dst);
    k_gemm1<<<(NN + 63) / 64, 256>>>(x, W1);
    k_conv1<<<NG * 4, 512, CONV1_SMEM>>>(b1, wrel, wroot);
    k_light<<<NG, 1024, LIGHT_SMEM>>>(brel, out);
    k_pool<<<NG * 8, 128>>>(W2, b2, out);
}